// round 5
// baseline (speedup 1.0000x reference)
#include <cuda_runtime.h>
#include <math.h>
#include <stdint.h>

#define B_ 2
#define C_ 96
#define D_ 8
#define H_ 48
#define W_ 48
#define L_ (D_*H_*W_)          // 18432
#define NROWS (B_*L_)          // 36864
#define DSTATE 16
#define DINNER 192
#define NC 72                  // scan chunks
#define CS (L_/NC)             // 256 steps per chunk

// ---------------- scratch ----------------
__device__ float g_h1[B_*C_*L_];            // dwconv out (raw, pre-GN)  (b,c,l)
__device__ float g_h2[B_*4*C_*L_];          // pw1 out               (b,o,l)
__device__ float g_xflat[NROWS*C_];         // x transposed          (row,c)
__device__ float g_xn[NROWS*C_];            // LN(x)                 (row,c)
__device__ float g_xzT[2*DINNER*NROWS];     // in_proj out T         [n][row]
__device__ float g_uT[DINNER*NROWS];        // silu(conv1d) T        [d][row]
__device__ float g_xdT[38*NROWS];           // x_proj out T          [r][row]
__device__ float g_dtT[DINNER*NROWS];       // softplus dt T         [d][row]
__device__ float g_yT[DINNER*NROWS];        // scan out gated T      [d][row]
__device__ float g_outm[NROWS*C_];          // out_proj out          (row,96)
__device__ float g_xm2[NROWS*C_];           // LN2 out               (row,96)
__device__ float g_stats[32];
__device__ float g_gnsc[B_*C_];
__device__ float g_gnsh[B_*C_];
__device__ float g_P[NC*384*DSTATE];
__device__ float g_F[NC*384*DSTATE];
__device__ float g_Hi[NC*384*DSTATE];

__device__ __forceinline__ float siluf(float x) { return x / (1.f + __expf(-x)); }
__device__ __forceinline__ float geluf(float x) {
    return 0.5f * x * (1.f + erff(x * 0.70710678118654752f));
}

typedef unsigned long long ull;
__device__ __forceinline__ ull packbc(float x) {
    ull r;
    asm("mov.b64 %0, {%1, %1};" : "=l"(r) : "f"(x));
    return r;
}
__device__ __forceinline__ float2 unpack2(ull v) {
    float2 r;
    asm("mov.b64 {%0, %1}, %2;" : "=f"(r.x), "=f"(r.y) : "l"(v));
    return r;
}
#define FMA2(d, a, b) asm("fma.rn.f32x2 %0, %1, %2, %0;" : "+l"(d) : "l"(a), "l"(b))

// ---------------- depthwise conv3d + bias + fused GN stats ----------------
__global__ __launch_bounds__(256) void dwconv3d_kernel(const float* __restrict__ x,
                                                       const float* __restrict__ w,
                                                       const float* __restrict__ bias) {
    __shared__ float s[10][22][22];
    __shared__ float wsm[147];
    __shared__ float r1[8], r2[8];
    int bc = blockIdx.z;
    int c = bc % C_;
    int b = bc / C_;
    int h0 = blockIdx.y * 16, w0 = blockIdx.x * 16;
    int tid = threadIdx.y * 16 + threadIdx.x;
    const float* xp = x + (size_t)bc * L_;
    for (int i = tid; i < 147; i += 256) wsm[i] = w[c*147 + i];
    for (int i = tid; i < 10*22*22; i += 256) {
        int dd = i / 484; int r = i % 484; int hh = r / 22; int ww = r % 22;
        int d = dd - 1, h = h0 + hh - 3, wq = w0 + ww - 3;
        float v = 0.f;
        if (d >= 0 && d < D_ && h >= 0 && h < H_ && wq >= 0 && wq < W_)
            v = xp[(d*H_ + h)*W_ + wq];
        s[dd][hh][ww] = v;
    }
    __syncthreads();
    int ty = threadIdx.y, tx = threadIdx.x;
    float bv = bias[c];
    float acc[8];
    #pragma unroll
    for (int i = 0; i < 8; i++) acc[i] = bv;
    #pragma unroll
    for (int dd = 0; dd < 10; dd++) {
        #pragma unroll
        for (int kh = 0; kh < 7; kh++) {
            #pragma unroll
            for (int kw = 0; kw < 7; kw++) {
                float v = s[dd][ty+kh][tx+kw];
                #pragma unroll
                for (int kd = 0; kd < 3; kd++) {
                    int od = dd - kd;
                    if (od >= 0 && od < 8)
                        acc[od] += v * wsm[kd*49 + kh*7 + kw];
                }
            }
        }
    }
    size_t base = (size_t)bc * L_;
    float s1 = 0.f, s2 = 0.f;
    #pragma unroll
    for (int od = 0; od < 8; od++) {
        g_h1[base + (od*H_ + h0 + ty)*W_ + (w0 + tx)] = acc[od];
        s1 += acc[od]; s2 += acc[od]*acc[od];
    }
    #pragma unroll
    for (int k = 16; k > 0; k >>= 1) {
        s1 += __shfl_xor_sync(0xffffffffu, s1, k);
        s2 += __shfl_xor_sync(0xffffffffu, s2, k);
    }
    if ((tid & 31) == 0) { r1[tid >> 5] = s1; r2[tid >> 5] = s2; }
    __syncthreads();
    if (tid == 0) {
        float t1 = 0.f, t2 = 0.f;
        #pragma unroll
        for (int i = 0; i < 8; i++) { t1 += r1[i]; t2 += r2[i]; }
        int z = b*8 + c/12;
        atomicAdd(&g_stats[z*2], t1);
        atomicAdd(&g_stats[z*2+1], t2);
    }
}

__global__ void zero_stats_kernel() { if (threadIdx.x < 32) g_stats[threadIdx.x] = 0.f; }

__global__ void gn_scale_kernel(const float* __restrict__ gg, const float* __restrict__ gb) {
    int i = threadIdx.x;
    if (i >= B_*C_) return;
    int b = i / C_, c = i % C_;
    int z = b*8 + c/12;
    float cnt = 12.f * (float)L_;
    float mu = g_stats[z*2] / cnt;
    float var = g_stats[z*2+1] / cnt - mu*mu;
    float inv = rsqrtf(var + 1e-5f);
    g_gnsc[i] = inv * gg[c];
    g_gnsh[i] = gb[c] - mu * inv * gg[c];
}

// ---------------- GEMM v3: 256 threads, BM=128, 8x(BN/16) microtile, f32x2 ----------
// A_KM : A stored [K, M]; else [M, K]
// OUT_NM: C stored [N, M]; else [M, N]
// ACT: 0 none, 1 exact gelu ; ACC: += into C ; NORM: per-k scale/shift on A (A_KM only)
template<bool A_KM, bool OUT_NM, int ACT, bool ACC, int BN, bool NORM>
__global__ __launch_bounds__(256, 2) void gemm3_kernel(
    const float* __restrict__ A, const float* __restrict__ Wt,
    const float* __restrict__ bias, float* __restrict__ Co,
    int M, int N, int K, size_t aBatch, size_t cBatch,
    const float* __restrict__ nscB, const float* __restrict__ nshB)
{
    constexpr int NCOL = BN / 16;        // 8 (BN=128) or 4 (BN=64)
    constexpr int WLD = BN / 64;         // W float4 loads per thread
    __shared__ float As[16][132];
    __shared__ float Ws[16][BN + 4];
    int m0 = blockIdx.x * 128, n0 = blockIdx.y * BN;
    A  += (size_t)blockIdx.z * aBatch;
    Co += (size_t)blockIdx.z * cBatch;
    const float* nsc = NORM ? (nscB + blockIdx.z * C_) : nullptr;
    const float* nsh = NORM ? (nshB + blockIdx.z * C_) : nullptr;
    int tid = threadIdx.x;
    int tn = tid & 15;
    int tm = tid >> 4;

    ull acc2[4][NCOL];                   // 4 row-pairs (8 rows) x NCOL cols
    #pragma unroll
    for (int rp = 0; rp < 4; rp++)
        #pragma unroll
        for (int c = 0; c < NCOL; c++) acc2[rp][c] = 0ull;

    for (int k0 = 0; k0 < K; k0 += 16) {
        // A tile: 16 x 128
        if (A_KM) {
            #pragma unroll
            for (int t = 0; t < 2; t++) {
                int f = tid + t*256;
                int kk = f >> 5; int p4 = (f & 31) << 2;
                float4 v = *(const float4*)(A + (size_t)(k0+kk)*M + m0 + p4);
                if (NORM) {
                    float sc = __ldg(&nsc[k0+kk]), sh = __ldg(&nsh[k0+kk]);
                    v.x = v.x*sc + sh; v.y = v.y*sc + sh;
                    v.z = v.z*sc + sh; v.w = v.w*sc + sh;
                }
                *(float4*)&As[kk][p4] = v;
            }
        } else {
            #pragma unroll
            for (int t = 0; t < 2; t++) {
                int f = tid + t*256;
                int mm = f >> 2; int q4 = (f & 3) << 2;
                float4 v = *(const float4*)(A + (size_t)(m0+mm)*K + k0 + q4);
                As[q4+0][mm] = v.x; As[q4+1][mm] = v.y;
                As[q4+2][mm] = v.z; As[q4+3][mm] = v.w;
            }
        }
        // W tile: BN x 16 (transposed into [k][n])
        #pragma unroll
        for (int t = 0; t < WLD; t++) {
            int f = tid + t*256;
            int nn = f >> 2; int q4 = (f & 3) << 2;
            float4 v = make_float4(0.f, 0.f, 0.f, 0.f);
            if (n0 + nn < N) v = *(const float4*)(Wt + (size_t)(n0+nn)*K + k0 + q4);
            Ws[q4+0][nn] = v.x; Ws[q4+1][nn] = v.y;
            Ws[q4+2][nn] = v.z; Ws[q4+3][nn] = v.w;
        }
        __syncthreads();
        #pragma unroll
        for (int kk = 0; kk < 16; kk++) {
            ull a2[4];
            const ull* ap = (const ull*)&As[kk][tm*8];
            #pragma unroll
            for (int i = 0; i < 4; i++) a2[i] = ap[i];
            ull w2[NCOL];
            #pragma unroll
            for (int h = 0; h < NCOL/4; h++) {
                float4 wv = *(const float4*)&Ws[kk][tn*NCOL + h*4];
                w2[h*4+0] = packbc(wv.x); w2[h*4+1] = packbc(wv.y);
                w2[h*4+2] = packbc(wv.z); w2[h*4+3] = packbc(wv.w);
            }
            #pragma unroll
            for (int rp = 0; rp < 4; rp++)
                #pragma unroll
                for (int c = 0; c < NCOL; c++)
                    FMA2(acc2[rp][c], a2[rp], w2[c]);
        }
        __syncthreads();
    }

    if (OUT_NM) {
        #pragma unroll
        for (int c = 0; c < NCOL; c++) {
            int n = n0 + tn*NCOL + c;
            if (n >= N) continue;
            float bv = bias ? bias[n] : 0.f;
            float* cp = Co + (size_t)n*M + m0 + tm*8;
            #pragma unroll
            for (int g = 0; g < 2; g++) {
                float2 lo = unpack2(acc2[g*2+0][c]);
                float2 hi = unpack2(acc2[g*2+1][c]);
                float4 v;
                v.x = lo.x + bv; v.y = lo.y + bv;
                v.z = hi.x + bv; v.w = hi.y + bv;
                if (ACT == 1) {
                    v.x = geluf(v.x); v.y = geluf(v.y);
                    v.z = geluf(v.z); v.w = geluf(v.w);
                }
                float* dst = cp + g*4;
                if (ACC) {
                    float4 o = *(float4*)dst;
                    v.x += o.x; v.y += o.y; v.z += o.z; v.w += o.w;
                }
                *(float4*)dst = v;
            }
        }
    } else {
        #pragma unroll
        for (int p = 0; p < 4; p++)
            #pragma unroll
            for (int e = 0; e < 2; e++) {
                int m = m0 + tm*8 + p*2 + e;
                float* rowp = Co + (size_t)m*N;
                #pragma unroll
                for (int h = 0; h < NCOL/4; h++) {
                    int nb = n0 + tn*NCOL + h*4;
                    float vv[4];
                    #pragma unroll
                    for (int j = 0; j < 4; j++) {
                        float2 uv = unpack2(acc2[p][h*4+j]);
                        float v = (e == 0) ? uv.x : uv.y;
                        if (nb + j < N) v += (bias ? bias[nb+j] : 0.f);
                        if (ACT == 1) v = geluf(v);
                        vv[j] = v;
                    }
                    if (nb + 3 < N) {
                        float4 v4 = make_float4(vv[0], vv[1], vv[2], vv[3]);
                        if (ACC) {
                            float4 o = *(float4*)(rowp + nb);
                            v4.x += o.x; v4.y += o.y; v4.z += o.z; v4.w += o.w;
                        }
                        *(float4*)(rowp + nb) = v4;
                    } else {
                        #pragma unroll
                        for (int j = 0; j < 4; j++) {
                            if (nb + j < N) {
                                float v = vv[j];
                                if (ACC) v += rowp[nb+j];
                                rowp[nb+j] = v;
                            }
                        }
                    }
                }
            }
    }
}

// ---------------- LayerNorm over C with transpose ----------------
__global__ __launch_bounds__(256) void ln1_kernel(const float* __restrict__ x,
                                                  const float* __restrict__ g,
                                                  const float* __restrict__ bta) {
    __shared__ float s[96][33];
    __shared__ float mu_s[32], rs_s[32];
    int b = blockIdx.y;
    int l0 = blockIdx.x * 32;
    int tid = threadIdx.x;
    int tx = tid & 31, ty = tid >> 5;
    const float* xp = x + (size_t)b * C_ * L_;
    for (int c = ty; c < C_; c += 8)
        s[c][tx] = xp[(size_t)c * L_ + l0 + tx];
    __syncthreads();
    if (tid < 32) {
        float sum = 0.f, sq = 0.f;
        #pragma unroll 4
        for (int c = 0; c < C_; c++) { float v = s[c][tid]; sum += v; sq += v*v; }
        float mu = sum / 96.f;
        float var = sq / 96.f - mu*mu;
        mu_s[tid] = mu; rs_s[tid] = rsqrtf(var + 1e-5f);
    }
    __syncthreads();
    for (int idx = tid; idx < 96*32; idx += 256) {
        int c = idx % 96, l = idx / 96;
        float v = s[c][l];
        size_t row = (size_t)(b*L_ + l0 + l);
        g_xflat[row*96 + c] = v;
        g_xn[row*96 + c] = (v - mu_s[l]) * rs_s[l] * g[c] + bta[c];
    }
}

// ---------------- causal depthwise conv1d (k=4) + SiLU ----------------
__global__ __launch_bounds__(256) void conv1d_kernel(const float* __restrict__ w,
                                                     const float* __restrict__ bias) {
    int idx = blockIdx.x * 256 + threadIdx.x;
    int lb = idx % (L_/4);
    int db = idx / (L_/4);
    if (db >= DINNER * B_) return;
    int b = db % B_, d = db / B_;
    const float* xp = g_xzT + (size_t)d*NROWS + (size_t)b*L_;
    float4 v = *(const float4*)(xp + lb*4);
    float4 p = make_float4(0.f, 0.f, 0.f, 0.f);
    if (lb > 0) p = *(const float4*)(xp + lb*4 - 4);
    float w0 = w[d*4+0], w1 = w[d*4+1], w2 = w[d*4+2], w3 = w[d*4+3];
    float bv = bias[d];
    float4 o;
    o.x = bv + p.y*w0 + p.z*w1 + p.w*w2 + v.x*w3;
    o.y = bv + p.z*w0 + p.w*w1 + v.x*w2 + v.y*w3;
    o.z = bv + p.w*w0 + v.x*w1 + v.y*w2 + v.z*w3;
    o.w = bv + v.x*w0 + v.y*w1 + v.z*w2 + v.w*w3;
    o.x = siluf(o.x); o.y = siluf(o.y); o.z = siluf(o.z); o.w = siluf(o.w);
    *(float4*)(g_uT + (size_t)d*NROWS + (size_t)b*L_ + lb*4) = o;
}

// ---------------- dt = softplus(x_dbl[:, :6] @ dt_proj_w^T + b), transposed out -------
__global__ __launch_bounds__(256) void dt2_kernel(const float* __restrict__ dtw,
                                                  const float* __restrict__ dtb) {
    __shared__ float ws[DINNER*6];
    __shared__ float bs[DINNER];
    int tid = threadIdx.x;
    int r0 = blockIdx.x * 256;
    for (int i = tid; i < DINNER*6; i += 256) ws[i] = dtw[i];
    if (tid < DINNER) bs[tid] = dtb[tid];
    __syncthreads();
    float x0 = g_xdT[0*NROWS + r0 + tid];
    float x1 = g_xdT[1*NROWS + r0 + tid];
    float x2 = g_xdT[2*NROWS + r0 + tid];
    float x3 = g_xdT[3*NROWS + r0 + tid];
    float x4 = g_xdT[4*NROWS + r0 + tid];
    float x5 = g_xdT[5*NROWS + r0 + tid];
    for (int d = 0; d < DINNER; d++) {
        float acc = bs[d];
        acc += x0*ws[d*6+0]; acc += x1*ws[d*6+1]; acc += x2*ws[d*6+2];
        acc += x3*ws[d*6+3]; acc += x4*ws[d*6+4]; acc += x5*ws[d*6+5];
        float sp = (acc > 20.f) ? acc : __logf(1.f + __expf(acc));
        g_dtT[(size_t)d*NROWS + r0 + tid] = sp;
    }
}

// ---------------- chunked selective scan ----------------
__global__ __launch_bounds__(128) void scan_phase1(const float* __restrict__ A_log) {
    int wid = (blockIdx.x * blockDim.x + threadIdx.x) >> 5;
    int lane = threadIdx.x & 31;
    int s = lane & 15, grp = lane >> 4;
    int pair = wid % 192;
    int chunk = wid / 192;
    int chan = pair*2 + grp;
    int b = chan / DINNER, d = chan % DINNER;
    float Aa = -expf(A_log[d*DSTATE + s]);
    float h = 0.f, P = 1.f;
    size_t base = (size_t)b*L_ + (size_t)chunk*CS;
    const float4* dtp = (const float4*)(g_dtT + (size_t)d*NROWS + base);
    const float4* up  = (const float4*)(g_uT  + (size_t)d*NROWS + base);
    const float4* bp  = (const float4*)(g_xdT + (size_t)(6+s)*NROWS + base);
    #pragma unroll 2
    for (int q = 0; q < CS/4; q++) {
        float4 dt4 = dtp[q], u4 = up[q], b4 = bp[q];
        float a;
        a = __expf(dt4.x*Aa); h = a*h + (dt4.x*u4.x)*b4.x; P *= a;
        a = __expf(dt4.y*Aa); h = a*h + (dt4.y*u4.y)*b4.y; P *= a;
        a = __expf(dt4.z*Aa); h = a*h + (dt4.z*u4.z)*b4.z; P *= a;
        a = __expf(dt4.w*Aa); h = a*h + (dt4.w*u4.w)*b4.w; P *= a;
    }
    int o = (chunk*384 + chan)*DSTATE + s;
    g_F[o] = h; g_P[o] = P;
}

__global__ __launch_bounds__(256) void scan_phase2() {
    int t = blockIdx.x * 256 + threadIdx.x;
    if (t >= 384*DSTATE) return;
    float H = 0.f;
    for (int j = 0; j < NC; j++) {
        int o = j*384*DSTATE + t;
        g_Hi[o] = H;
        H = g_F[o] + g_P[o]*H;
    }
}

__global__ __launch_bounds__(128) void scan_phase3(const float* __restrict__ A_log,
                                                   const float* __restrict__ Dp) {
    int wid = (blockIdx.x * blockDim.x + threadIdx.x) >> 5;
    int lane = threadIdx.x & 31;
    int s = lane & 15, grp = lane >> 4;
    int pair = wid % 192;
    int chunk = wid / 192;
    int chan = pair*2 + grp;
    int b = chan / DINNER, d = chan % DINNER;
    float Aa = -expf(A_log[d*DSTATE + s]);
    float Dpd = Dp[d];
    float h = g_Hi[(chunk*384 + chan)*DSTATE + s];
    size_t base = (size_t)b*L_ + (size_t)chunk*CS;
    const float4* dtp = (const float4*)(g_dtT + (size_t)d*NROWS + base);
    const float4* up  = (const float4*)(g_uT  + (size_t)d*NROWS + base);
    const float4* bp  = (const float4*)(g_xdT + (size_t)(6+s)*NROWS + base);
    const float4* cp  = (const float4*)(g_xdT + (size_t)(22+s)*NROWS + base);
    const float4* zp  = (const float4*)(g_xzT + (size_t)(192+d)*NROWS + base);
    float4* yp = (float4*)(g_yT + (size_t)d*NROWS + base);
    for (int q = 0; q < CS/4; q++) {
        float4 dt4 = dtp[q], u4 = up[q], b4 = bp[q], c4 = cp[q], z4 = zp[q];
        float4 yv;
        float a, p;
        a = __expf(dt4.x*Aa); h = a*h + (dt4.x*u4.x)*b4.x;
        p = h * c4.x;
        p += __shfl_xor_sync(0xffffffffu, p, 8);
        p += __shfl_xor_sync(0xffffffffu, p, 4);
        p += __shfl_xor_sync(0xffffffffu, p, 2);
        p += __shfl_xor_sync(0xffffffffu, p, 1);
        yv.x = (p + u4.x*Dpd) * siluf(z4.x);
        a = __expf(dt4.y*Aa); h = a*h + (dt4.y*u4.y)*b4.y;
        p = h * c4.y;
        p += __shfl_xor_sync(0xffffffffu, p, 8);
        p += __shfl_xor_sync(0xffffffffu, p, 4);
        p += __shfl_xor_sync(0xffffffffu, p, 2);
        p += __shfl_xor_sync(0xffffffffu, p, 1);
        yv.y = (p + u4.y*Dpd) * siluf(z4.y);
        a = __expf(dt4.z*Aa); h = a*h + (dt4.z*u4.z)*b4.z;
        p = h * c4.z;
        p += __shfl_xor_sync(0xffffffffu, p, 8);
        p += __shfl_xor_sync(0xffffffffu, p, 4);
        p += __shfl_xor_sync(0xffffffffu, p, 2);
        p += __shfl_xor_sync(0xffffffffu, p, 1);
        yv.z = (p + u4.z*Dpd) * siluf(z4.z);
        a = __expf(dt4.w*Aa); h = a*h + (dt4.w*u4.w)*b4.w;
        p = h * c4.w;
        p += __shfl_xor_sync(0xffffffffu, p, 8);
        p += __shfl_xor_sync(0xffffffffu, p, 4);
        p += __shfl_xor_sync(0xffffffffu, p, 2);
        p += __shfl_xor_sync(0xffffffffu, p, 1);
        yv.w = (p + u4.w*Dpd) * siluf(z4.w);
        if (s == 0) yp[q] = yv;
    }
}

// ---------------- residual + LayerNorm (warp per row) ----------------
__global__ __launch_bounds__(256) void ln2_kernel(const float* __restrict__ g,
                                                  const float* __restrict__ bta,
                                                  const float* __restrict__ skip) {
    int warp = (int)((blockIdx.x * blockDim.x + threadIdx.x) >> 5);
    int lane = threadIdx.x & 31;
    if (warp >= NROWS) return;
    float sk = skip[0];
    size_t base = (size_t)warp * 96;
    float t[3]; float sum = 0.f, sq = 0.f;
    #pragma unroll
    for (int i = 0; i < 3; i++) {
        int c = lane + 32*i;
        t[i] = g_outm[base+c] + sk * g_xflat[base+c];
        sum += t[i]; sq += t[i]*t[i];
    }
    #pragma unroll
    for (int k = 16; k > 0; k >>= 1) {
        sum += __shfl_xor_sync(0xffffffffu, sum, k);
        sq  += __shfl_xor_sync(0xffffffffu, sq,  k);
    }
    float mu = sum / 96.f;
    float var = sq / 96.f - mu*mu;
    float inv = rsqrtf(var + 1e-5f);
    #pragma unroll
    for (int i = 0; i < 3; i++) {
        int c = lane + 32*i;
        g_xm2[base+c] = (t[i] - mu) * inv * g[c] + bta[c];
    }
}

// ---------------- launch ----------------
extern "C" void kernel_launch(void* const* d_in, const int* in_sizes, int n_in,
                              void* d_out, int out_size) {
    const float* x     = (const float*)d_in[0];
    const float* dw_w  = (const float*)d_in[1];
    const float* dw_b  = (const float*)d_in[2];
    const float* gn_g  = (const float*)d_in[3];
    const float* gn_b  = (const float*)d_in[4];
    const float* pw1_w = (const float*)d_in[5];
    const float* pw1_b = (const float*)d_in[6];
    const float* pw2_w = (const float*)d_in[7];
    const float* pw2_b = (const float*)d_in[8];
    const float* ln_g  = (const float*)d_in[9];
    const float* ln_b  = (const float*)d_in[10];
    const float* skip  = (const float*)d_in[11];
    const float* inpw  = (const float*)d_in[12];
    const float* c1w   = (const float*)d_in[13];
    const float* c1b   = (const float*)d_in[14];
    const float* xpw   = (const float*)d_in[15];
    const float* dtw   = (const float*)d_in[16];
    const float* dtb   = (const float*)d_in[17];
    const float* A_log = (const float*)d_in[18];
    const float* Dp    = (const float*)d_in[19];
    const float* outpw = (const float*)d_in[20];
    const float* projw = (const float*)d_in[21];
    const float* projb = (const float*)d_in[22];
    float* out = (float*)d_out;

    float *p_h1, *p_h2, *p_xn, *p_xzT, *p_uT, *p_xdT, *p_yT, *p_outm, *p_xm2, *p_sc, *p_sh;
    cudaGetSymbolAddress((void**)&p_h1,   g_h1);
    cudaGetSymbolAddress((void**)&p_h2,   g_h2);
    cudaGetSymbolAddress((void**)&p_xn,   g_xn);
    cudaGetSymbolAddress((void**)&p_xzT,  g_xzT);
    cudaGetSymbolAddress((void**)&p_uT,   g_uT);
    cudaGetSymbolAddress((void**)&p_xdT,  g_xdT);
    cudaGetSymbolAddress((void**)&p_yT,   g_yT);
    cudaGetSymbolAddress((void**)&p_outm, g_outm);
    cudaGetSymbolAddress((void**)&p_xm2,  g_xm2);
    cudaGetSymbolAddress((void**)&p_sc,   g_gnsc);
    cudaGetSymbolAddress((void**)&p_sh,   g_gnsh);

    // ---- conv branch ----
    zero_stats_kernel<<<1,32>>>();
    dwconv3d_kernel<<<dim3(3,3,B_*C_), dim3(16,16)>>>(x, dw_w, dw_b);
    gn_scale_kernel<<<1,256>>>(gn_g, gn_b);
    gemm3_kernel<true,true,1,false,128,true><<<dim3(L_/128, 3, B_),256>>>(
        p_h1, pw1_w, pw1_b, p_h2, L_, 4*C_, C_, (size_t)C_*L_, (size_t)4*C_*L_, p_sc, p_sh);
    gemm3_kernel<true,true,0,false,128,false><<<dim3(L_/128, 1, B_),256>>>(
        p_h2, pw2_w, pw2_b, out, L_, C_, 4*C_, (size_t)4*C_*L_, (size_t)C_*L_, nullptr, nullptr);

    // ---- mamba branch ----
    ln1_kernel<<<dim3(L_/32, B_),256>>>(x, ln_g, ln_b);
    gemm3_kernel<false,true,0,false,128,false><<<dim3(NROWS/128, 3, 1),256>>>(
        p_xn, inpw, nullptr, p_xzT, NROWS, 2*DINNER, C_, 0, 0, nullptr, nullptr);
    conv1d_kernel<<<(DINNER*B_*(L_/4))/256,256>>>(c1w, c1b);
    gemm3_kernel<true,true,0,false,64,false><<<dim3(NROWS/128, 1, 1),256>>>(
        p_uT, xpw, nullptr, p_xdT, NROWS, 38, DINNER, 0, 0, nullptr, nullptr);
    dt2_kernel<<<NROWS/256,256>>>(dtw, dtb);
    scan_phase1<<<(192*NC)/4, 128>>>(A_log);
    scan_phase2<<<24,256>>>();
    scan_phase3<<<(192*NC)/4, 128>>>(A_log, Dp);
    gemm3_kernel<true,false,0,false,128,false><<<dim3(NROWS/128, 1, 1),256>>>(
        p_yT, outpw, nullptr, p_outm, NROWS, C_, DINNER, 0, 0, nullptr, nullptr);
    ln2_kernel<<<NROWS/8,256>>>(ln_g, ln_b, skip);
    gemm3_kernel<false,true,0,true,128,false><<<dim3(L_/128, 1, B_),256>>>(
        p_xm2, projw, projb, out, L_, C_, C_, (size_t)L_*C_, (size_t)C_*L_, nullptr, nullptr);
}

// round 6
// speedup vs baseline: 1.1799x; 1.1799x over previous
#include <cuda_runtime.h>
#include <math.h>
#include <stdint.h>

#define B_ 2
#define C_ 96
#define D_ 8
#define H_ 48
#define W_ 48
#define L_ (D_*H_*W_)          // 18432
#define NROWS (B_*L_)          // 36864
#define DSTATE 16
#define DINNER 192
#define NC 72
#define CS (L_/NC)             // 256

// ---------------- scratch ----------------
__device__ float g_h1[B_*C_*L_];
__device__ float g_h2[B_*4*C_*L_];
__device__ float g_xflat[NROWS*C_];
__device__ float g_xn[NROWS*C_];
__device__ float g_xzT[2*DINNER*NROWS];
__device__ float g_uT[DINNER*NROWS];
__device__ float g_xdT[38*NROWS];
__device__ float g_dtT[DINNER*NROWS];
__device__ float g_yT[DINNER*NROWS];
__device__ float g_outm[NROWS*C_];
__device__ float g_xm2[NROWS*C_];
__device__ float g_stats[32];
__device__ float g_gnsc[B_*C_];
__device__ float g_gnsh[B_*C_];
__device__ float g_P[NC*384*DSTATE];
__device__ float g_F[NC*384*DSTATE];
__device__ float g_Hi[NC*384*DSTATE];

__device__ __forceinline__ float siluf(float x) { return x / (1.f + __expf(-x)); }
__device__ __forceinline__ float geluf(float x) {
    return 0.5f * x * (1.f + erff(x * 0.70710678118654752f));
}
__device__ __forceinline__ unsigned f2tf(float x) {
    unsigned r;
    asm("cvt.rna.tf32.f32 %0, %1;" : "=r"(r) : "f"(x));
    return r;
}
__device__ __forceinline__ void mma_tf32(float c[4], const unsigned a[4], const unsigned b[2]) {
    asm("mma.sync.aligned.m16n8k8.row.col.f32.tf32.tf32.f32 "
        "{%0,%1,%2,%3}, {%4,%5,%6,%7}, {%8,%9}, {%0,%1,%2,%3};"
        : "+f"(c[0]), "+f"(c[1]), "+f"(c[2]), "+f"(c[3])
        : "r"(a[0]), "r"(a[1]), "r"(a[2]), "r"(a[3]), "r"(b[0]), "r"(b[1]));
}

// ---------------- depthwise conv3d + bias + fused GN stats ----------------
__global__ __launch_bounds__(256) void dwconv3d_kernel(const float* __restrict__ x,
                                                       const float* __restrict__ w,
                                                       const float* __restrict__ bias) {
    __shared__ float s[10][22][22];
    __shared__ float wsm[147];
    __shared__ float r1[8], r2[8];
    int bc = blockIdx.z;
    int c = bc % C_;
    int b = bc / C_;
    int h0 = blockIdx.y * 16, w0 = blockIdx.x * 16;
    int tid = threadIdx.y * 16 + threadIdx.x;
    const float* xp = x + (size_t)bc * L_;
    for (int i = tid; i < 147; i += 256) wsm[i] = w[c*147 + i];
    for (int i = tid; i < 10*22*22; i += 256) {
        int dd = i / 484; int r = i % 484; int hh = r / 22; int ww = r % 22;
        int d = dd - 1, h = h0 + hh - 3, wq = w0 + ww - 3;
        float v = 0.f;
        if (d >= 0 && d < D_ && h >= 0 && h < H_ && wq >= 0 && wq < W_)
            v = xp[(d*H_ + h)*W_ + wq];
        s[dd][hh][ww] = v;
    }
    __syncthreads();
    int ty = threadIdx.y, tx = threadIdx.x;
    float bv = bias[c];
    float acc[8];
    #pragma unroll
    for (int i = 0; i < 8; i++) acc[i] = bv;
    #pragma unroll
    for (int dd = 0; dd < 10; dd++) {
        #pragma unroll
        for (int kh = 0; kh < 7; kh++) {
            #pragma unroll
            for (int kw = 0; kw < 7; kw++) {
                float v = s[dd][ty+kh][tx+kw];
                #pragma unroll
                for (int kd = 0; kd < 3; kd++) {
                    int od = dd - kd;
                    if (od >= 0 && od < 8)
                        acc[od] += v * wsm[kd*49 + kh*7 + kw];
                }
            }
        }
    }
    size_t base = (size_t)bc * L_;
    float s1 = 0.f, s2 = 0.f;
    #pragma unroll
    for (int od = 0; od < 8; od++) {
        g_h1[base + (od*H_ + h0 + ty)*W_ + (w0 + tx)] = acc[od];
        s1 += acc[od]; s2 += acc[od]*acc[od];
    }
    #pragma unroll
    for (int k = 16; k > 0; k >>= 1) {
        s1 += __shfl_xor_sync(0xffffffffu, s1, k);
        s2 += __shfl_xor_sync(0xffffffffu, s2, k);
    }
    if ((tid & 31) == 0) { r1[tid >> 5] = s1; r2[tid >> 5] = s2; }
    __syncthreads();
    if (tid == 0) {
        float t1 = 0.f, t2 = 0.f;
        #pragma unroll
        for (int i = 0; i < 8; i++) { t1 += r1[i]; t2 += r2[i]; }
        int z = b*8 + c/12;
        atomicAdd(&g_stats[z*2], t1);
        atomicAdd(&g_stats[z*2+1], t2);
    }
}

__global__ void zero_stats_kernel() { if (threadIdx.x < 32) g_stats[threadIdx.x] = 0.f; }

__global__ void gn_scale_kernel(const float* __restrict__ gg, const float* __restrict__ gb) {
    int i = threadIdx.x;
    if (i >= B_*C_) return;
    int b = i / C_, c = i % C_;
    int z = b*8 + c/12;
    float cnt = 12.f * (float)L_;
    float mu = g_stats[z*2] / cnt;
    float var = g_stats[z*2+1] / cnt - mu*mu;
    float inv = rsqrtf(var + 1e-5f);
    g_gnsc[i] = inv * gg[c];
    g_gnsh[i] = gb[c] - mu * inv * gg[c];
}

// ---------------- GEMM v4: tf32 mma.sync, 256 thr, BM=BN=128, warp 64x32 ----------
// A_KM : A stored [K, M]; else [M, K].  OUT_NM: C stored [N, M]; else [M, N].
// ACT: 0 none, 1 gelu.  ACC: += into C.  NORM: per-k scale/shift on A (A_KM only).
template<bool A_KM, bool OUT_NM, int ACT, bool ACC, bool NORM>
__global__ __launch_bounds__(256, 2) void gemmt_kernel(
    const float* __restrict__ A, const float* __restrict__ Wt,
    const float* __restrict__ bias, float* __restrict__ Co,
    int M, int N, int K, size_t aBatch, size_t cBatch,
    const float* __restrict__ nscB, const float* __restrict__ nshB)
{
    __shared__ unsigned As[16][136];
    __shared__ unsigned Ws[16][136];
    int m0 = blockIdx.x * 128, n0 = blockIdx.y * 128;
    A  += (size_t)blockIdx.z * aBatch;
    Co += (size_t)blockIdx.z * cBatch;
    const float* nsc = NORM ? (nscB + blockIdx.z * C_) : nullptr;
    const float* nsh = NORM ? (nshB + blockIdx.z * C_) : nullptr;
    int tid = threadIdx.x;
    int lane = tid & 31;
    int warp = tid >> 5;
    int wm = (warp & 1) * 64;            // warp m offset within block tile
    int wn = (warp >> 1) * 32;           // warp n offset

    float cacc[4][4][4];                 // [mt][nt][frag]
    #pragma unroll
    for (int mt = 0; mt < 4; mt++)
        #pragma unroll
        for (int nt = 0; nt < 4; nt++)
            #pragma unroll
            for (int e = 0; e < 4; e++) cacc[mt][nt][e] = 0.f;

    for (int k0 = 0; k0 < K; k0 += 16) {
        // ---- stage A tile (16 x 128) as tf32 ----
        if (A_KM) {
            #pragma unroll
            for (int t = 0; t < 2; t++) {
                int f = tid + t*256;
                int kk = f >> 5; int p4 = (f & 31) << 2;
                float4 v = *(const float4*)(A + (size_t)(k0+kk)*M + m0 + p4);
                if (NORM) {
                    float sc = __ldg(&nsc[k0+kk]), sh = __ldg(&nsh[k0+kk]);
                    v.x = v.x*sc + sh; v.y = v.y*sc + sh;
                    v.z = v.z*sc + sh; v.w = v.w*sc + sh;
                }
                As[kk][p4+0] = f2tf(v.x); As[kk][p4+1] = f2tf(v.y);
                As[kk][p4+2] = f2tf(v.z); As[kk][p4+3] = f2tf(v.w);
            }
        } else {
            #pragma unroll
            for (int t = 0; t < 2; t++) {
                int f = tid + t*256;
                int mm = f >> 2; int q4 = (f & 3) << 2;
                float4 v = *(const float4*)(A + (size_t)(m0+mm)*K + k0 + q4);
                As[q4+0][mm] = f2tf(v.x); As[q4+1][mm] = f2tf(v.y);
                As[q4+2][mm] = f2tf(v.z); As[q4+3][mm] = f2tf(v.w);
            }
        }
        // ---- stage W tile (128 x 16 -> [k][n]) as tf32, zero-pad n >= N ----
        #pragma unroll
        for (int t = 0; t < 2; t++) {
            int f = tid + t*256;
            int nn = f >> 2; int q4 = (f & 3) << 2;
            float4 v = make_float4(0.f, 0.f, 0.f, 0.f);
            if (n0 + nn < N) v = *(const float4*)(Wt + (size_t)(n0+nn)*K + k0 + q4);
            Ws[q4+0][nn] = f2tf(v.x); Ws[q4+1][nn] = f2tf(v.y);
            Ws[q4+2][nn] = f2tf(v.z); Ws[q4+3][nn] = f2tf(v.w);
        }
        __syncthreads();
        // ---- two k8 sub-steps ----
        #pragma unroll
        for (int ks = 0; ks < 2; ks++) {
            int kk = ks * 8;
            int r = lane >> 2, cq = lane & 3;
            unsigned af[4][4];
            #pragma unroll
            for (int mt = 0; mt < 4; mt++) {
                int mb = wm + mt*16;
                af[mt][0] = As[kk + cq    ][mb + r];
                af[mt][1] = As[kk + cq    ][mb + r + 8];
                af[mt][2] = As[kk + cq + 4][mb + r];
                af[mt][3] = As[kk + cq + 4][mb + r + 8];
            }
            unsigned bf[4][2];
            #pragma unroll
            for (int nt = 0; nt < 4; nt++) {
                int nb = wn + nt*8;
                bf[nt][0] = Ws[kk + cq    ][nb + r];
                bf[nt][1] = Ws[kk + cq + 4][nb + r];
            }
            #pragma unroll
            for (int mt = 0; mt < 4; mt++)
                #pragma unroll
                for (int nt = 0; nt < 4; nt++)
                    mma_tf32(cacc[mt][nt], af[mt], bf[nt]);
        }
        __syncthreads();
    }

    // ---- epilogue ----
    int r = lane >> 2, j2 = (lane & 3) * 2;
    #pragma unroll
    for (int mt = 0; mt < 4; mt++)
        #pragma unroll
        for (int nt = 0; nt < 4; nt++) {
            int mb = m0 + wm + mt*16 + r;
            int nb = n0 + wn + nt*8 + j2;
            #pragma unroll
            for (int e = 0; e < 4; e++) {
                int m = mb + ((e >> 1) ? 8 : 0);
                int n = nb + (e & 1);
                if (n < N) {
                    float v = cacc[mt][nt][e] + (bias ? bias[n] : 0.f);
                    if (ACT == 1) v = geluf(v);
                    size_t off = OUT_NM ? ((size_t)n*M + m) : ((size_t)m*N + n);
                    if (ACC) v += Co[off];
                    Co[off] = v;
                }
            }
        }
}

// ---------------- LayerNorm over C with transpose ----------------
__global__ __launch_bounds__(256) void ln1_kernel(const float* __restrict__ x,
                                                  const float* __restrict__ g,
                                                  const float* __restrict__ bta) {
    __shared__ float s[96][33];
    __shared__ float mu_s[32], rs_s[32];
    int b = blockIdx.y;
    int l0 = blockIdx.x * 32;
    int tid = threadIdx.x;
    int tx = tid & 31, ty = tid >> 5;
    const float* xp = x + (size_t)b * C_ * L_;
    for (int c = ty; c < C_; c += 8)
        s[c][tx] = xp[(size_t)c * L_ + l0 + tx];
    __syncthreads();
    if (tid < 32) {
        float sum = 0.f, sq = 0.f;
        #pragma unroll 4
        for (int c = 0; c < C_; c++) { float v = s[c][tid]; sum += v; sq += v*v; }
        float mu = sum / 96.f;
        float var = sq / 96.f - mu*mu;
        mu_s[tid] = mu; rs_s[tid] = rsqrtf(var + 1e-5f);
    }
    __syncthreads();
    for (int idx = tid; idx < 96*32; idx += 256) {
        int c = idx % 96, l = idx / 96;
        float v = s[c][l];
        size_t row = (size_t)(b*L_ + l0 + l);
        g_xflat[row*96 + c] = v;
        g_xn[row*96 + c] = (v - mu_s[l]) * rs_s[l] * g[c] + bta[c];
    }
}

// ---------------- causal depthwise conv1d (k=4) + SiLU ----------------
__global__ __launch_bounds__(256) void conv1d_kernel(const float* __restrict__ w,
                                                     const float* __restrict__ bias) {
    int idx = blockIdx.x * 256 + threadIdx.x;
    int lb = idx % (L_/4);
    int db = idx / (L_/4);
    if (db >= DINNER * B_) return;
    int b = db % B_, d = db / B_;
    const float* xp = g_xzT + (size_t)d*NROWS + (size_t)b*L_;
    float4 v = *(const float4*)(xp + lb*4);
    float4 p = make_float4(0.f, 0.f, 0.f, 0.f);
    if (lb > 0) p = *(const float4*)(xp + lb*4 - 4);
    float w0 = w[d*4+0], w1 = w[d*4+1], w2 = w[d*4+2], w3 = w[d*4+3];
    float bv = bias[d];
    float4 o;
    o.x = bv + p.y*w0 + p.z*w1 + p.w*w2 + v.x*w3;
    o.y = bv + p.z*w0 + p.w*w1 + v.x*w2 + v.y*w3;
    o.z = bv + p.w*w0 + v.x*w1 + v.y*w2 + v.z*w3;
    o.w = bv + v.x*w0 + v.y*w1 + v.z*w2 + v.w*w3;
    o.x = siluf(o.x); o.y = siluf(o.y); o.z = siluf(o.z); o.w = siluf(o.w);
    *(float4*)(g_uT + (size_t)d*NROWS + (size_t)b*L_ + lb*4) = o;
}

// ---------------- dt = softplus(x_dbl[:, :6] @ dt_proj_w^T + b), transposed out -------
__global__ __launch_bounds__(256) void dt2_kernel(const float* __restrict__ dtw,
                                                  const float* __restrict__ dtb) {
    __shared__ float ws[DINNER*6];
    __shared__ float bs[DINNER];
    int tid = threadIdx.x;
    int r0 = blockIdx.x * 256;
    for (int i = tid; i < DINNER*6; i += 256) ws[i] = dtw[i];
    if (tid < DINNER) bs[tid] = dtb[tid];
    __syncthreads();
    float x0 = g_xdT[0*NROWS + r0 + tid];
    float x1 = g_xdT[1*NROWS + r0 + tid];
    float x2 = g_xdT[2*NROWS + r0 + tid];
    float x3 = g_xdT[3*NROWS + r0 + tid];
    float x4 = g_xdT[4*NROWS + r0 + tid];
    float x5 = g_xdT[5*NROWS + r0 + tid];
    for (int d = 0; d < DINNER; d++) {
        float acc = bs[d];
        acc += x0*ws[d*6+0]; acc += x1*ws[d*6+1]; acc += x2*ws[d*6+2];
        acc += x3*ws[d*6+3]; acc += x4*ws[d*6+4]; acc += x5*ws[d*6+5];
        float sp = (acc > 20.f) ? acc : __logf(1.f + __expf(acc));
        g_dtT[(size_t)d*NROWS + r0 + tid] = sp;
    }
}

// ---------------- chunked selective scan ----------------
__global__ __launch_bounds__(128) void scan_phase1(const float* __restrict__ A_log) {
    int wid = (blockIdx.x * blockDim.x + threadIdx.x) >> 5;
    int lane = threadIdx.x & 31;
    int s = lane & 15, grp = lane >> 4;
    int pair = wid % 192;
    int chunk = wid / 192;
    int chan = pair*2 + grp;
    int b = chan / DINNER, d = chan % DINNER;
    float Aa = -expf(A_log[d*DSTATE + s]);
    float h = 0.f, P = 1.f;
    size_t base = (size_t)b*L_ + (size_t)chunk*CS;
    const float4* dtp = (const float4*)(g_dtT + (size_t)d*NROWS + base);
    const float4* up  = (const float4*)(g_uT  + (size_t)d*NROWS + base);
    const float4* bp  = (const float4*)(g_xdT + (size_t)(6+s)*NROWS + base);
    #pragma unroll 2
    for (int q = 0; q < CS/4; q++) {
        float4 dt4 = dtp[q], u4 = up[q], b4 = bp[q];
        float a;
        a = __expf(dt4.x*Aa); h = a*h + (dt4.x*u4.x)*b4.x; P *= a;
        a = __expf(dt4.y*Aa); h = a*h + (dt4.y*u4.y)*b4.y; P *= a;
        a = __expf(dt4.z*Aa); h = a*h + (dt4.z*u4.z)*b4.z; P *= a;
        a = __expf(dt4.w*Aa); h = a*h + (dt4.w*u4.w)*b4.w; P *= a;
    }
    int o = (chunk*384 + chan)*DSTATE + s;
    g_F[o] = h; g_P[o] = P;
}

__global__ __launch_bounds__(256) void scan_phase2() {
    int t = blockIdx.x * 256 + threadIdx.x;
    if (t >= 384*DSTATE) return;
    float H = 0.f;
    for (int j = 0; j < NC; j++) {
        int o = j*384*DSTATE + t;
        g_Hi[o] = H;
        H = g_F[o] + g_P[o]*H;
    }
}

__global__ __launch_bounds__(128) void scan_phase3(const float* __restrict__ A_log,
                                                   const float* __restrict__ Dp) {
    int wid = (blockIdx.x * blockDim.x + threadIdx.x) >> 5;
    int lane = threadIdx.x & 31;
    int s = lane & 15, grp = lane >> 4;
    int pair = wid % 192;
    int chunk = wid / 192;
    int chan = pair*2 + grp;
    int b = chan / DINNER, d = chan % DINNER;
    float Aa = -expf(A_log[d*DSTATE + s]);
    float Dpd = Dp[d];
    float h = g_Hi[(chunk*384 + chan)*DSTATE + s];
    size_t base = (size_t)b*L_ + (size_t)chunk*CS;
    const float4* dtp = (const float4*)(g_dtT + (size_t)d*NROWS + base);
    const float4* up  = (const float4*)(g_uT  + (size_t)d*NROWS + base);
    const float4* bp  = (const float4*)(g_xdT + (size_t)(6+s)*NROWS + base);
    const float4* cp  = (const float4*)(g_xdT + (size_t)(22+s)*NROWS + base);
    const float4* zp  = (const float4*)(g_xzT + (size_t)(192+d)*NROWS + base);
    float4* yp = (float4*)(g_yT + (size_t)d*NROWS + base);
    for (int q = 0; q < CS/4; q++) {
        float4 dt4 = dtp[q], u4 = up[q], b4 = bp[q], c4 = cp[q], z4 = zp[q];
        float4 yv;
        float a, p;
        a = __expf(dt4.x*Aa); h = a*h + (dt4.x*u4.x)*b4.x;
        p = h * c4.x;
        p += __shfl_xor_sync(0xffffffffu, p, 8);
        p += __shfl_xor_sync(0xffffffffu, p, 4);
        p += __shfl_xor_sync(0xffffffffu, p, 2);
        p += __shfl_xor_sync(0xffffffffu, p, 1);
        yv.x = (p + u4.x*Dpd) * siluf(z4.x);
        a = __expf(dt4.y*Aa); h = a*h + (dt4.y*u4.y)*b4.y;
        p = h * c4.y;
        p += __shfl_xor_sync(0xffffffffu, p, 8);
        p += __shfl_xor_sync(0xffffffffu, p, 4);
        p += __shfl_xor_sync(0xffffffffu, p, 2);
        p += __shfl_xor_sync(0xffffffffu, p, 1);
        yv.y = (p + u4.y*Dpd) * siluf(z4.y);
        a = __expf(dt4.z*Aa); h = a*h + (dt4.z*u4.z)*b4.z;
        p = h * c4.z;
        p += __shfl_xor_sync(0xffffffffu, p, 8);
        p += __shfl_xor_sync(0xffffffffu, p, 4);
        p += __shfl_xor_sync(0xffffffffu, p, 2);
        p += __shfl_xor_sync(0xffffffffu, p, 1);
        yv.z = (p + u4.z*Dpd) * siluf(z4.z);
        a = __expf(dt4.w*Aa); h = a*h + (dt4.w*u4.w)*b4.w;
        p = h * c4.w;
        p += __shfl_xor_sync(0xffffffffu, p, 8);
        p += __shfl_xor_sync(0xffffffffu, p, 4);
        p += __shfl_xor_sync(0xffffffffu, p, 2);
        p += __shfl_xor_sync(0xffffffffu, p, 1);
        yv.w = (p + u4.w*Dpd) * siluf(z4.w);
        if (s == 0) yp[q] = yv;
    }
}

// ---------------- residual + LayerNorm (warp per row) ----------------
__global__ __launch_bounds__(256) void ln2_kernel(const float* __restrict__ g,
                                                  const float* __restrict__ bta,
                                                  const float* __restrict__ skip) {
    int warp = (int)((blockIdx.x * blockDim.x + threadIdx.x) >> 5);
    int lane = threadIdx.x & 31;
    if (warp >= NROWS) return;
    float sk = skip[0];
    size_t base = (size_t)warp * 96;
    float t[3]; float sum = 0.f, sq = 0.f;
    #pragma unroll
    for (int i = 0; i < 3; i++) {
        int c = lane + 32*i;
        t[i] = g_outm[base+c] + sk * g_xflat[base+c];
        sum += t[i]; sq += t[i]*t[i];
    }
    #pragma unroll
    for (int k = 16; k > 0; k >>= 1) {
        sum += __shfl_xor_sync(0xffffffffu, sum, k);
        sq  += __shfl_xor_sync(0xffffffffu, sq,  k);
    }
    float mu = sum / 96.f;
    float var = sq / 96.f - mu*mu;
    float inv = rsqrtf(var + 1e-5f);
    #pragma unroll
    for (int i = 0; i < 3; i++) {
        int c = lane + 32*i;
        g_xm2[base+c] = (t[i] - mu) * inv * g[c] + bta[c];
    }
}

// ---------------- launch ----------------
extern "C" void kernel_launch(void* const* d_in, const int* in_sizes, int n_in,
                              void* d_out, int out_size) {
    const float* x     = (const float*)d_in[0];
    const float* dw_w  = (const float*)d_in[1];
    const float* dw_b  = (const float*)d_in[2];
    const float* gn_g  = (const float*)d_in[3];
    const float* gn_b  = (const float*)d_in[4];
    const float* pw1_w = (const float*)d_in[5];
    const float* pw1_b = (const float*)d_in[6];
    const float* pw2_w = (const float*)d_in[7];
    const float* pw2_b = (const float*)d_in[8];
    const float* ln_g  = (const float*)d_in[9];
    const float* ln_b  = (const float*)d_in[10];
    const float* skip  = (const float*)d_in[11];
    const float* inpw  = (const float*)d_in[12];
    const float* c1w   = (const float*)d_in[13];
    const float* c1b   = (const float*)d_in[14];
    const float* xpw   = (const float*)d_in[15];
    const float* dtw   = (const float*)d_in[16];
    const float* dtb   = (const float*)d_in[17];
    const float* A_log = (const float*)d_in[18];
    const float* Dp    = (const float*)d_in[19];
    const float* outpw = (const float*)d_in[20];
    const float* projw = (const float*)d_in[21];
    const float* projb = (const float*)d_in[22];
    float* out = (float*)d_out;

    float *p_h1, *p_h2, *p_xn, *p_xzT, *p_uT, *p_xdT, *p_yT, *p_outm, *p_xm2, *p_sc, *p_sh;
    cudaGetSymbolAddress((void**)&p_h1,   g_h1);
    cudaGetSymbolAddress((void**)&p_h2,   g_h2);
    cudaGetSymbolAddress((void**)&p_xn,   g_xn);
    cudaGetSymbolAddress((void**)&p_xzT,  g_xzT);
    cudaGetSymbolAddress((void**)&p_uT,   g_uT);
    cudaGetSymbolAddress((void**)&p_xdT,  g_xdT);
    cudaGetSymbolAddress((void**)&p_yT,   g_yT);
    cudaGetSymbolAddress((void**)&p_outm, g_outm);
    cudaGetSymbolAddress((void**)&p_xm2,  g_xm2);
    cudaGetSymbolAddress((void**)&p_sc,   g_gnsc);
    cudaGetSymbolAddress((void**)&p_sh,   g_gnsh);

    // ---- conv branch ----
    zero_stats_kernel<<<1,32>>>();
    dwconv3d_kernel<<<dim3(3,3,B_*C_), dim3(16,16)>>>(x, dw_w, dw_b);
    gn_scale_kernel<<<1,256>>>(gn_g, gn_b);
    gemmt_kernel<true,true,1,false,true><<<dim3(L_/128, 3, B_),256>>>(
        p_h1, pw1_w, pw1_b, p_h2, L_, 4*C_, C_, (size_t)C_*L_, (size_t)4*C_*L_, p_sc, p_sh);
    gemmt_kernel<true,true,0,false,false><<<dim3(L_/128, 1, B_),256>>>(
        p_h2, pw2_w, pw2_b, out, L_, C_, 4*C_, (size_t)4*C_*L_, (size_t)C_*L_, nullptr, nullptr);

    // ---- mamba branch ----
    ln1_kernel<<<dim3(L_/32, B_),256>>>(x, ln_g, ln_b);
    gemmt_kernel<false,true,0,false,false><<<dim3(NROWS/128, 3, 1),256>>>(
        p_xn, inpw, nullptr, p_xzT, NROWS, 2*DINNER, C_, 0, 0, nullptr, nullptr);
    conv1d_kernel<<<(DINNER*B_*(L_/4))/256,256>>>(c1w, c1b);
    gemmt_kernel<true,true,0,false,false><<<dim3(NROWS/128, 1, 1),256>>>(
        p_uT, xpw, nullptr, p_xdT, NROWS, 38, DINNER, 0, 0, nullptr, nullptr);
    dt2_kernel<<<NROWS/256,256>>>(dtw, dtb);
    scan_phase1<<<(192*NC)/4, 128>>>(A_log);
    scan_phase2<<<24,256>>>();
    scan_phase3<<<(192*NC)/4, 128>>>(A_log, Dp);
    gemmt_kernel<true,false,0,false,false><<<dim3(NROWS/128, 1, 1),256>>>(
        p_yT, outpw, nullptr, p_outm, NROWS, C_, DINNER, 0, 0, nullptr, nullptr);
    ln2_kernel<<<NROWS/8,256>>>(ln_g, ln_b, skip);
    gemmt_kernel<false,true,0,true,false><<<dim3(L_/128, 1, B_),256>>>(
        p_xm2, projw, projb, out, L_, C_, C_, (size_t)L_*C_, (size_t)C_*L_, nullptr, nullptr);
}